// round 9
// baseline (speedup 1.0000x reference)
#include <cuda_runtime.h>
#include <cuda_fp16.h>
#include <cstdint>

#define CDIM 256
#define HW 4096
#define NPIX 65536
#define KCODES 1024
#define NTILES 512
#define LOSS_OFF 16777216
#define IDX_OFF  16777217

// scratch (__device__ globals; no cudaMalloc allowed)
__device__ __half  g_A[(size_t)NPIX * 512];     // [pixel][xh(256)|xl(256)]   64 MB
__device__ __half  g_B[(size_t)KCODES * 768];   // [code][Eh|Eh|El]           1.5 MB
__device__ float   g_s1[NPIX];
__device__ float   g_s2[KCODES];
__device__ float   g_cand_d[NPIX * 8];
__device__ int     g_cand_i[NPIX * 8];
__device__ int     g_idx[NPIX];
__device__ double  g_partial[NTILES];

__device__ __forceinline__ uint32_t smem_u32(const void* p) {
    uint32_t a;
    asm("{ .reg .u64 t; cvta.to.shared.u64 t, %1; cvt.u32.u64 %0, t; }" : "=r"(a) : "l"(p));
    return a;
}

#define LDSM4(r0, r1, r2, r3, addr) \
    asm volatile("ldmatrix.sync.aligned.m8n8.x4.shared.b16 {%0,%1,%2,%3}, [%4];" \
        : "=r"(r0), "=r"(r1), "=r"(r2), "=r"(r3) : "r"(addr))

#define MMA16816(c0, c1, c2, c3, a0, a1, a2, a3, b0, b1) \
    asm volatile("mma.sync.aligned.m16n8k16.row.col.f32.f16.f16.f32 " \
        "{%0,%1,%2,%3}, {%4,%5,%6,%7}, {%8,%9}, {%0,%1,%2,%3};" \
        : "+f"(c0), "+f"(c1), "+f"(c2), "+f"(c3) \
        : "r"(a0), "r"(a1), "r"(a2), "r"(a3), "r"(b0), "r"(b1))

// ---------------------------------------------------------------------------
// split codebook -> fp16 hi/lo (x1024) + ||e||^2   (proven)
// ---------------------------------------------------------------------------
__global__ void k_split_b(const float* __restrict__ cb, __half* __restrict__ B_,
                          float* __restrict__ s2g) {
    int k = blockIdx.x * 256 + threadIdx.x;
    if (k >= KCODES) return;
    const float* row = cb + (size_t)k * CDIM;
    __half* o = B_ + (size_t)k * 768;
    float s = 0.f;
    for (int d = 0; d < CDIM; ++d) {
        float e = row[d];
        s += e * e;
        float E = e * 1024.0f;
        __half eh = __float2half_rn(E);
        __half el = __float2half_rn(E - __half2float(eh));
        o[d] = eh; o[256 + d] = eh; o[512 + d] = el;
    }
    s2g[k] = s;
}

// ---------------------------------------------------------------------------
// split inputs -> fp16 hi/lo [pixel][d]; s1 sequential-d   (proven R8)
// ---------------------------------------------------------------------------
__global__ void __launch_bounds__(256)
k_split_a(const float* __restrict__ in, __half* __restrict__ A_,
          float* __restrict__ s1g) {
    extern __shared__ float xs[];   // [256 d][stride 69]
    const int tid = threadIdx.x;
    const int blk = blockIdx.x;                 // 1024 blocks of 64 pixels
    const int b = blk >> 6, hw0 = (blk & 63) << 6;
    const float* inb = in + ((size_t)b << 20);

    for (int t = tid; t < 256 * 16; t += 256) {
        int d = t >> 4, p4 = t & 15;
        float4 v = *(const float4*)(inb + (size_t)d * HW + hw0 + p4 * 4);
        float* dst = xs + d * 69 + p4 * 4;
        dst[0] = v.x; dst[1] = v.y; dst[2] = v.z; dst[3] = v.w;
    }
    __syncthreads();

    if (tid < 64) {
        float s = 0.f;
        for (int d = 0; d < CDIM; ++d) { float v = xs[d * 69 + tid]; s += v * v; }
        s1g[blk * 64 + tid] = s;
    }

    const int d = tid;
    for (int i = 0; i < 64; ++i) {
        float x = xs[d * 69 + i];
        __half xh = __float2half_rn(x);
        __half xl = __float2half_rn(x - __half2float(xh));
        size_t row = ((size_t)(blk * 64 + i)) << 9;   // *512
        A_[row + d] = xh;
        A_[row + 256 + d] = xl;
    }
}

// ---------------------------------------------------------------------------
// HMMA GEMM tile: 128 px x 128 codes; 4 warps (128 thr), warp tile 64x64.
// Same smem layout, same chunk order, bit-identical accumulation chains.
// smem: [0,1KB) rd | [1KB,2KB) ri | [2KB,2.5KB) s2 | [4KB) 2 x 36864 stages
// ---------------------------------------------------------------------------
__device__ __forceinline__ void load_chunk(uint32_t sb, const char* Ag, const char* Bg,
                                           int p0, int nt, int kc, int buf, int tid) {
    const uint32_t sA = sb + 4096 + buf * 36864;
    const uint32_t sB = sA + 18432;
    const size_t aoff = (size_t)(kc & 7) * 128;
    const size_t boff = (size_t)kc * 128;
    #pragma unroll
    for (int i = 0; i < 8; ++i) {
        int o = tid + 128 * i;           // 0..1023
        int row = o >> 3, seg = (o & 7) * 16;
        const char* src = Ag + ((size_t)(p0 + row) << 10) + aoff + seg;
        uint32_t dst = sA + row * 144 + seg;
        asm volatile("cp.async.cg.shared.global [%0], [%1], 16;" :: "r"(dst), "l"(src));
    }
    #pragma unroll
    for (int i = 0; i < 8; ++i) {
        int o = tid + 128 * i;
        int row = o >> 3, seg = (o & 7) * 16;
        const char* src = Bg + (size_t)(nt * 128 + row) * 1536 + boff + seg;
        uint32_t dst = sB + row * 144 + seg;
        asm volatile("cp.async.cg.shared.global [%0], [%1], 16;" :: "r"(dst), "l"(src));
    }
}

__global__ void __launch_bounds__(128, 2)
k_gemm(const __half* __restrict__ Ah, const __half* __restrict__ Bh,
       const float* __restrict__ s1g, const float* __restrict__ s2g,
       float* __restrict__ cand_d, int* __restrict__ cand_i) {
    extern __shared__ char sm[];
    uint32_t sb = smem_u32(sm);
    float* rd = (float*)sm;
    int*   ri = (int*)(sm + 1024);
    float* s2s = (float*)(sm + 2048);

    const int tid = threadIdx.x, lane = tid & 31, wid = tid >> 5;
    const int warp_m = wid & 1, warp_n = wid >> 1;    // 2M x 2N warp grid
    const int m0 = warp_m * 64, n0 = warp_n * 64;
    const int blk = blockIdx.x, pb = blk >> 3, nt = blk & 7;   // 8 code tiles
    const int p0 = pb * 128;
    const char* Ag = (const char*)Ah;
    const char* Bg = (const char*)Bh;

    s2s[tid] = s2g[nt * 128 + tid];

    // ldmatrix per-thread offsets (within a stage tile)
    const int rA = (lane & 7) + ((lane >> 3) & 1) * 8;    // 0..15
    const int cA = (lane >> 4) * 16;                      // 0 or 16 bytes (k8)
    uint32_t aoffs[4];
    #pragma unroll
    for (int f = 0; f < 4; ++f) aoffs[f] = (m0 + f * 16 + rA) * 144 + cA;
    const int rB = (lane & 7) + ((lane >> 4) << 3);       // 0..15
    const int cB = ((lane >> 3) & 1) * 16;                // 0 or 16 bytes (k8)
    uint32_t boff[4];
    #pragma unroll
    for (int g = 0; g < 4; ++g) boff[g] = (n0 + g * 16 + rB) * 144 + cB;

    // s1 for the 8 row-slots this thread owns (slot s = 2*mf + b; row = m0+mf*16+(lane>>2)+b*8)
    float s1v[8];
    #pragma unroll
    for (int s = 0; s < 8; ++s)
        s1v[s] = s1g[p0 + m0 + (s >> 1) * 16 + (lane >> 2) + (s & 1) * 8];

    float c[4][8][4];
    #pragma unroll
    for (int mf = 0; mf < 4; ++mf)
        #pragma unroll
        for (int j = 0; j < 8; ++j)
            #pragma unroll
            for (int q = 0; q < 4; ++q) c[mf][j][q] = 0.f;

    load_chunk(sb, Ag, Bg, p0, nt, 0, 0, tid);
    asm volatile("cp.async.commit_group;" ::: "memory");

    for (int kc = 0; kc < 12; ++kc) {
        const int buf = kc & 1;
        __syncthreads();
        if (kc + 1 < 12) {
            load_chunk(sb, Ag, Bg, p0, nt, kc + 1, buf ^ 1, tid);
            asm volatile("cp.async.commit_group;" ::: "memory");
            asm volatile("cp.async.wait_group 1;" ::: "memory");
        } else {
            asm volatile("cp.async.wait_group 0;" ::: "memory");
        }
        __syncthreads();

        const uint32_t sA = sb + 4096 + buf * 36864;
        const uint32_t sB = sA + 18432;
        #pragma unroll
        for (int ks = 0; ks < 4; ++ks) {
            uint32_t a[4][4], bf[4][4];
            #pragma unroll
            for (int f = 0; f < 4; ++f)
                LDSM4(a[f][0], a[f][1], a[f][2], a[f][3], sA + aoffs[f] + ks * 32);
            #pragma unroll
            for (int g = 0; g < 4; ++g)
                LDSM4(bf[g][0], bf[g][1], bf[g][2], bf[g][3], sB + boff[g] + ks * 32);

            #pragma unroll
            for (int f = 0; f < 4; ++f) {
                #pragma unroll
                for (int g = 0; g < 4; ++g) {
                    MMA16816(c[f][2*g][0], c[f][2*g][1], c[f][2*g][2], c[f][2*g][3],
                             a[f][0], a[f][1], a[f][2], a[f][3], bf[g][0], bf[g][1]);
                    MMA16816(c[f][2*g+1][0], c[f][2*g+1][1], c[f][2*g+1][2], c[f][2*g+1][3],
                             a[f][0], a[f][1], a[f][2], a[f][3], bf[g][2], bf[g][3]);
                }
            }
        }
    }

    // fold into per-thread argmin (ascending local n -> first-index tie-break)
    const float SC = 0.001953125f;   // 2^-9
    float bd[8];
    int   bi[8];
    #pragma unroll
    for (int s = 0; s < 8; ++s) { bd[s] = 3.4e38f; bi[s] = 0; }
    #pragma unroll
    for (int mf = 0; mf < 4; ++mf) {
        #pragma unroll
        for (int j = 0; j < 8; ++j) {
            const int nl = n0 + j * 8 + ((lane & 3) << 1);
            const float s2a = s2s[nl], s2b = s2s[nl + 1];
            const int sl0 = mf * 2, sl1 = mf * 2 + 1;
            float d0 = (s1v[sl0] + s2a) - c[mf][j][0] * SC;
            float d1 = (s1v[sl0] + s2b) - c[mf][j][1] * SC;
            float d2 = (s1v[sl1] + s2a) - c[mf][j][2] * SC;
            float d3 = (s1v[sl1] + s2b) - c[mf][j][3] * SC;
            if (d0 < bd[sl0]) { bd[sl0] = d0; bi[sl0] = nl; }
            if (d1 < bd[sl0]) { bd[sl0] = d1; bi[sl0] = nl + 1; }
            if (d2 < bd[sl1]) { bd[sl1] = d2; bi[sl1] = nl; }
            if (d3 < bd[sl1]) { bd[sl1] = d3; bi[sl1] = nl + 1; }
        }
    }
    // quad reduce (lanes sharing a row differ only in lane&3), lexicographic
    #pragma unroll
    for (int s = 0; s < 8; ++s) {
        #pragma unroll
        for (int off = 1; off <= 2; off <<= 1) {
            float od = __shfl_xor_sync(0xffffffffu, bd[s], off);
            int   oi = __shfl_xor_sync(0xffffffffu, bi[s], off);
            if (od < bd[s] || (od == bd[s] && oi < bi[s])) { bd[s] = od; bi[s] = oi; }
        }
    }
    __syncthreads();
    if ((lane & 3) == 0) {
        #pragma unroll
        for (int s = 0; s < 8; ++s) {
            int row = m0 + (s >> 1) * 16 + (lane >> 2) + (s & 1) * 8;
            rd[row * 2 + warp_n] = bd[s];
            ri[row * 2 + warp_n] = bi[s];
        }
    }
    __syncthreads();
    {
        float d0 = rd[tid * 2], d1 = rd[tid * 2 + 1];
        int i0 = ri[tid * 2], i1 = ri[tid * 2 + 1];
        bool t1 = (d1 < d0 || (d1 == d0 && i1 < i0));
        cand_d[(size_t)(p0 + tid) * 8 + nt] = t1 ? d1 : d0;
        cand_i[(size_t)(p0 + tid) * 8 + nt] = nt * 128 + (t1 ? i1 : i0);
    }
}

// ---------------------------------------------------------------------------
// combine 8 candidates per pixel -> final index (+ indices-as-float output)
// ---------------------------------------------------------------------------
__global__ void k_combine(const float* __restrict__ cand_d, const int* __restrict__ cand_i,
                          int* __restrict__ gidx, float* __restrict__ out) {
    int p = blockIdx.x * 256 + threadIdx.x;
    size_t base = (size_t)p * 8;
    float bdv = cand_d[base]; int biv = cand_i[base];
    #pragma unroll
    for (int t = 1; t < 8; ++t) {
        float d = cand_d[base + t]; int i = cand_i[base + t];
        if (d < bdv || (d == bdv && i < biv)) { bdv = d; biv = i; }
    }
    gidx[p] = biv;
    out[IDX_OFF + p] = (float)biv;
}

// ---------------------------------------------------------------------------
// gather quantized output + loss partials   (proven R4 body)
// ---------------------------------------------------------------------------
__global__ void __launch_bounds__(256)
k_out(const float* __restrict__ in, const float* __restrict__ cb,
      const int* __restrict__ gidx, float* __restrict__ out,
      double* __restrict__ partial) {
    __shared__ int idxs[128];
    __shared__ double red[256];
    const int tid = threadIdx.x;
    const int blk = blockIdx.x;
    const int b = blk >> 5, hw0 = (blk & 31) << 7;

    if (tid < 128) idxs[tid] = gidx[(b << 12) + hw0 + tid];
    __syncthreads();

    const float* inb  = in  + ((size_t)b << 20);
    float*       outb = out + ((size_t)b << 20);

    double acc = 0.0;
    for (int t = tid; t < CDIM * 128; t += 256) {
        int d = t >> 7, p = t & 127;
        float q = cb[(size_t)idxs[p] * CDIM + d];
        float x = inb[(size_t)d * HW + hw0 + p];
        outb[(size_t)d * HW + hw0 + p] = q;
        float df = q - x;
        acc += (double)df * (double)df;
    }

    red[tid] = acc;
    __syncthreads();
    #pragma unroll
    for (int s = 128; s > 0; s >>= 1) {
        if (tid < s) red[tid] += red[tid + s];
        __syncthreads();
    }
    if (tid == 0) partial[blk] = red[0];
}

__global__ void k_final(const double* __restrict__ partial, float* __restrict__ out) {
    __shared__ double red[256];
    int tid = threadIdx.x;
    double a = 0.0;
    for (int t = tid; t < NTILES; t += 256) a += partial[t];
    red[tid] = a;
    __syncthreads();
    #pragma unroll
    for (int s = 128; s > 0; s >>= 1) {
        if (tid < s) red[tid] += red[tid + s];
        __syncthreads();
    }
    if (tid == 0) {
        double mse = red[0] / (double)(NPIX * (double)CDIM);
        out[LOSS_OFF] = (float)(1.25 * mse);
    }
}

// ---------------------------------------------------------------------------
extern "C" void kernel_launch(void* const* d_in, const int* in_sizes, int n_in,
                              void* d_out, int out_size) {
    (void)in_sizes; (void)n_in; (void)out_size;
    const float* in = (const float*)d_in[0];
    const float* cb = (const float*)d_in[1];
    float* out = (float*)d_out;

    __half* A_p; __half* B_p;
    float *s1_p, *s2_p, *cd_p; int *ci_p, *idx_p; double* part_p;
    cudaGetSymbolAddress((void**)&A_p,   g_A);
    cudaGetSymbolAddress((void**)&B_p,   g_B);
    cudaGetSymbolAddress((void**)&s1_p,  g_s1);
    cudaGetSymbolAddress((void**)&s2_p,  g_s2);
    cudaGetSymbolAddress((void**)&cd_p,  g_cand_d);
    cudaGetSymbolAddress((void**)&ci_p,  g_cand_i);
    cudaGetSymbolAddress((void**)&idx_p, g_idx);
    cudaGetSymbolAddress((void**)&part_p, g_partial);

    const int smem_a = 256 * 69 * 4;             // 70656 -> 3 CTAs/SM
    const int smem_g = 4096 + 2 * 36864;         // 77824
    cudaFuncSetAttribute(k_split_a, cudaFuncAttributeMaxDynamicSharedMemorySize, smem_a);
    cudaFuncSetAttribute(k_gemm,    cudaFuncAttributeMaxDynamicSharedMemorySize, smem_g);

    k_split_b<<<4, 256>>>(cb, B_p, s2_p);
    k_split_a<<<1024, 256, smem_a>>>(in, A_p, s1_p);
    k_gemm<<<4096, 128, smem_g>>>(A_p, B_p, s1_p, s2_p, cd_p, ci_p);
    k_combine<<<256, 256>>>(cd_p, ci_p, idx_p, out);
    k_out<<<NTILES, 256>>>(in, cb, idx_p, out, part_p);
    k_final<<<1, 256>>>(part_p, out);
}

// round 10
// speedup vs baseline: 1.0662x; 1.0662x over previous
#include <cuda_runtime.h>
#include <cuda_fp16.h>
#include <cstdint>

#define CDIM 256
#define HW 4096
#define NPIX 65536
#define KCODES 1024
#define NTILES 512
#define LOSS_OFF 16777216
#define IDX_OFF  16777217

// scratch (__device__ globals; no cudaMalloc allowed)
__device__ __half  g_A[(size_t)NPIX * 512];     // [pixel][xh(256)|xl(256)]   64 MB
__device__ __half  g_B[(size_t)KCODES * 768];   // [code][Eh|Eh|El]           1.5 MB
__device__ float   g_s1[NPIX];
__device__ float   g_s2[KCODES];
__device__ float   g_cand_d[NPIX * 8];
__device__ int     g_cand_i[NPIX * 8];
__device__ int     g_idx[NPIX];
__device__ double  g_partial[NTILES];

__device__ __forceinline__ uint32_t smem_u32(const void* p) {
    uint32_t a;
    asm("{ .reg .u64 t; cvta.to.shared.u64 t, %1; cvt.u32.u64 %0, t; }" : "=r"(a) : "l"(p));
    return a;
}

#define LDSM4(r0, r1, r2, r3, addr) \
    asm volatile("ldmatrix.sync.aligned.m8n8.x4.shared.b16 {%0,%1,%2,%3}, [%4];" \
        : "=r"(r0), "=r"(r1), "=r"(r2), "=r"(r3) : "r"(addr))

#define MMA16816(c0, c1, c2, c3, a0, a1, a2, a3, b0, b1) \
    asm volatile("mma.sync.aligned.m16n8k16.row.col.f32.f16.f16.f32 " \
        "{%0,%1,%2,%3}, {%4,%5,%6,%7}, {%8,%9}, {%0,%1,%2,%3};" \
        : "+f"(c0), "+f"(c1), "+f"(c2), "+f"(c3) \
        : "r"(a0), "r"(a1), "r"(a2), "r"(a3), "r"(b0), "r"(b1))

// ---------------------------------------------------------------------------
// instrumentation no-op: shifts k_gemm to captured launch index 3
// ---------------------------------------------------------------------------
__global__ void k_nop() {}

// ---------------------------------------------------------------------------
// split codebook -> fp16 hi/lo (x1024) + ||e||^2   (proven)
// ---------------------------------------------------------------------------
__global__ void k_split_b(const float* __restrict__ cb, __half* __restrict__ B_,
                          float* __restrict__ s2g) {
    int k = blockIdx.x * 256 + threadIdx.x;
    if (k >= KCODES) return;
    const float* row = cb + (size_t)k * CDIM;
    __half* o = B_ + (size_t)k * 768;
    float s = 0.f;
    for (int d = 0; d < CDIM; ++d) {
        float e = row[d];
        s += e * e;
        float E = e * 1024.0f;
        __half eh = __float2half_rn(E);
        __half el = __float2half_rn(E - __half2float(eh));
        o[d] = eh; o[256 + d] = eh; o[512 + d] = el;
    }
    s2g[k] = s;
}

// ---------------------------------------------------------------------------
// split inputs -> fp16 hi/lo [pixel][d]; s1 sequential-d   (proven R8)
// ---------------------------------------------------------------------------
__global__ void __launch_bounds__(256)
k_split_a(const float* __restrict__ in, __half* __restrict__ A_,
          float* __restrict__ s1g) {
    extern __shared__ float xs[];   // [256 d][stride 69]
    const int tid = threadIdx.x;
    const int blk = blockIdx.x;                 // 1024 blocks of 64 pixels
    const int b = blk >> 6, hw0 = (blk & 63) << 6;
    const float* inb = in + ((size_t)b << 20);

    for (int t = tid; t < 256 * 16; t += 256) {
        int d = t >> 4, p4 = t & 15;
        float4 v = *(const float4*)(inb + (size_t)d * HW + hw0 + p4 * 4);
        float* dst = xs + d * 69 + p4 * 4;
        dst[0] = v.x; dst[1] = v.y; dst[2] = v.z; dst[3] = v.w;
    }
    __syncthreads();

    if (tid < 64) {
        float s = 0.f;
        for (int d = 0; d < CDIM; ++d) { float v = xs[d * 69 + tid]; s += v * v; }
        s1g[blk * 64 + tid] = s;
    }

    const int d = tid;
    for (int i = 0; i < 64; ++i) {
        float x = xs[d * 69 + i];
        __half xh = __float2half_rn(x);
        __half xl = __float2half_rn(x - __half2float(xh));
        size_t row = ((size_t)(blk * 64 + i)) << 9;   // *512
        A_[row + d] = xh;
        A_[row + 256 + d] = xl;
    }
}

// ---------------------------------------------------------------------------
// HMMA GEMM tile: 128 px x 128 codes; 4 warps, warp tile 64x64.
// 3-stage XOR-swizzled pipeline, ONE __syncthreads per chunk.
// smem: [0,1KB) rd | [1KB,2KB) ri | [2KB,2.5KB) s2 | [4KB) 3 x 32768 stages
// stage: A 128 rows x 128B @0 | B 128 rows x 128B @16384; swizzle seg^((row&7)<<4)
// ---------------------------------------------------------------------------
__device__ __forceinline__ void load_chunk3(uint32_t st, const char* Ag, const char* Bg,
                                            int p0, int nt, int kc, int tid) {
    const size_t aoff = (size_t)(kc & 7) * 128;
    const size_t boff = (size_t)kc * 128;
    #pragma unroll
    for (int i = 0; i < 8; ++i) {
        int o = tid + 128 * i;           // 0..1023
        int row = o >> 3, seg = (o & 7) * 16;
        const char* src = Ag + ((size_t)(p0 + row) << 10) + aoff + seg;
        uint32_t dst = st + row * 128 + (seg ^ ((row & 7) << 4));
        asm volatile("cp.async.cg.shared.global [%0], [%1], 16;" :: "r"(dst), "l"(src));
    }
    #pragma unroll
    for (int i = 0; i < 8; ++i) {
        int o = tid + 128 * i;
        int row = o >> 3, seg = (o & 7) * 16;
        const char* src = Bg + (size_t)(nt * 128 + row) * 1536 + boff + seg;
        uint32_t dst = st + 16384 + row * 128 + (seg ^ ((row & 7) << 4));
        asm volatile("cp.async.cg.shared.global [%0], [%1], 16;" :: "r"(dst), "l"(src));
    }
}

__global__ void __launch_bounds__(128, 2)
k_gemm(const __half* __restrict__ Ah, const __half* __restrict__ Bh,
       const float* __restrict__ s1g, const float* __restrict__ s2g,
       float* __restrict__ cand_d, int* __restrict__ cand_i) {
    extern __shared__ char sm[];
    uint32_t sb = smem_u32(sm);
    float* rd = (float*)sm;
    int*   ri = (int*)(sm + 1024);
    float* s2s = (float*)(sm + 2048);
    const uint32_t stg = sb + 4096;

    const int tid = threadIdx.x, lane = tid & 31, wid = tid >> 5;
    const int warp_m = wid & 1, warp_n = wid >> 1;    // 2M x 2N warp grid
    const int m0 = warp_m * 64, n0 = warp_n * 64;
    const int blk = blockIdx.x, pb = blk >> 3, nt = blk & 7;   // 8 code tiles
    const int p0 = pb * 128;
    const char* Ag = (const char*)Ah;
    const char* Bg = (const char*)Bh;

    s2s[tid] = s2g[nt * 128 + tid];

    // ldmatrix per-thread row bases + swizzle masks
    const int rA = (lane & 7) + ((lane >> 3) & 1) * 8;    // 0..15
    const int cA = (lane >> 4) * 16;                      // 0 or 16 (k8 halves)
    const int mA = (rA & 7) << 4;
    uint32_t arow[4];
    #pragma unroll
    for (int f = 0; f < 4; ++f) arow[f] = (uint32_t)(m0 + f * 16 + rA) * 128;
    const int rB = (lane & 7) + ((lane >> 4) << 3);       // 0..15
    const int cB = ((lane >> 3) & 1) * 16;
    const int mB = (rB & 7) << 4;
    uint32_t brow[4];
    #pragma unroll
    for (int g = 0; g < 4; ++g) brow[g] = (uint32_t)(n0 + g * 16 + rB) * 128;

    float s1v[8];
    #pragma unroll
    for (int s = 0; s < 8; ++s)
        s1v[s] = s1g[p0 + m0 + (s >> 1) * 16 + (lane >> 2) + (s & 1) * 8];

    float c[4][8][4];
    #pragma unroll
    for (int mf = 0; mf < 4; ++mf)
        #pragma unroll
        for (int j = 0; j < 8; ++j)
            #pragma unroll
            for (int q = 0; q < 4; ++q) c[mf][j][q] = 0.f;

    // prologue: chunks 0,1 into stages 0,1
    load_chunk3(stg,         Ag, Bg, p0, nt, 0, tid);
    asm volatile("cp.async.commit_group;" ::: "memory");
    load_chunk3(stg + 32768, Ag, Bg, p0, nt, 1, tid);
    asm volatile("cp.async.commit_group;" ::: "memory");

    for (int kc = 0; kc < 12; ++kc) {
        if (kc < 11) asm volatile("cp.async.wait_group 1;" ::: "memory");
        else         asm volatile("cp.async.wait_group 0;" ::: "memory");
        __syncthreads();   // chunk kc visible everywhere; all warps past compute kc-1
        if (kc + 2 < 12) {
            load_chunk3(stg + ((kc + 2) % 3) * 32768, Ag, Bg, p0, nt, kc + 2, tid);
            asm volatile("cp.async.commit_group;" ::: "memory");
        }

        const uint32_t sA = stg + (kc % 3) * 32768;
        const uint32_t sB = sA + 16384;
        #pragma unroll
        for (int ks = 0; ks < 4; ++ks) {
            const uint32_t colA = (uint32_t)((cA + ks * 32) ^ mA);
            const uint32_t colB = (uint32_t)((cB + ks * 32) ^ mB);
            uint32_t a[4][4], bf[4][4];
            #pragma unroll
            for (int f = 0; f < 4; ++f)
                LDSM4(a[f][0], a[f][1], a[f][2], a[f][3], sA + arow[f] + colA);
            #pragma unroll
            for (int g = 0; g < 4; ++g)
                LDSM4(bf[g][0], bf[g][1], bf[g][2], bf[g][3], sB + brow[g] + colB);

            #pragma unroll
            for (int f = 0; f < 4; ++f) {
                #pragma unroll
                for (int g = 0; g < 4; ++g) {
                    MMA16816(c[f][2*g][0], c[f][2*g][1], c[f][2*g][2], c[f][2*g][3],
                             a[f][0], a[f][1], a[f][2], a[f][3], bf[g][0], bf[g][1]);
                    MMA16816(c[f][2*g+1][0], c[f][2*g+1][1], c[f][2*g+1][2], c[f][2*g+1][3],
                             a[f][0], a[f][1], a[f][2], a[f][3], bf[g][2], bf[g][3]);
                }
            }
        }
    }

    // fold into per-thread argmin (ascending local n -> first-index tie-break)
    const float SC = 0.001953125f;   // 2^-9
    float bd[8];
    int   bi[8];
    #pragma unroll
    for (int s = 0; s < 8; ++s) { bd[s] = 3.4e38f; bi[s] = 0; }
    #pragma unroll
    for (int mf = 0; mf < 4; ++mf) {
        #pragma unroll
        for (int j = 0; j < 8; ++j) {
            const int nl = n0 + j * 8 + ((lane & 3) << 1);
            const float s2a = s2s[nl], s2b = s2s[nl + 1];
            const int sl0 = mf * 2, sl1 = mf * 2 + 1;
            float d0 = (s1v[sl0] + s2a) - c[mf][j][0] * SC;
            float d1 = (s1v[sl0] + s2b) - c[mf][j][1] * SC;
            float d2 = (s1v[sl1] + s2a) - c[mf][j][2] * SC;
            float d3 = (s1v[sl1] + s2b) - c[mf][j][3] * SC;
            if (d0 < bd[sl0]) { bd[sl0] = d0; bi[sl0] = nl; }
            if (d1 < bd[sl0]) { bd[sl0] = d1; bi[sl0] = nl + 1; }
            if (d2 < bd[sl1]) { bd[sl1] = d2; bi[sl1] = nl; }
            if (d3 < bd[sl1]) { bd[sl1] = d3; bi[sl1] = nl + 1; }
        }
    }
    #pragma unroll
    for (int s = 0; s < 8; ++s) {
        #pragma unroll
        for (int off = 1; off <= 2; off <<= 1) {
            float od = __shfl_xor_sync(0xffffffffu, bd[s], off);
            int   oi = __shfl_xor_sync(0xffffffffu, bi[s], off);
            if (od < bd[s] || (od == bd[s] && oi < bi[s])) { bd[s] = od; bi[s] = oi; }
        }
    }
    __syncthreads();
    if ((lane & 3) == 0) {
        #pragma unroll
        for (int s = 0; s < 8; ++s) {
            int row = m0 + (s >> 1) * 16 + (lane >> 2) + (s & 1) * 8;
            rd[row * 2 + warp_n] = bd[s];
            ri[row * 2 + warp_n] = bi[s];
        }
    }
    __syncthreads();
    {
        float d0 = rd[tid * 2], d1 = rd[tid * 2 + 1];
        int i0 = ri[tid * 2], i1 = ri[tid * 2 + 1];
        bool t1 = (d1 < d0 || (d1 == d0 && i1 < i0));
        cand_d[(size_t)(p0 + tid) * 8 + nt] = t1 ? d1 : d0;
        cand_i[(size_t)(p0 + tid) * 8 + nt] = nt * 128 + (t1 ? i1 : i0);
    }
}

// ---------------------------------------------------------------------------
// combine 8 candidates per pixel -> final index (+ indices-as-float output)
// ---------------------------------------------------------------------------
__global__ void k_combine(const float* __restrict__ cand_d, const int* __restrict__ cand_i,
                          int* __restrict__ gidx, float* __restrict__ out) {
    int p = blockIdx.x * 256 + threadIdx.x;
    size_t base = (size_t)p * 8;
    float bdv = cand_d[base]; int biv = cand_i[base];
    #pragma unroll
    for (int t = 1; t < 8; ++t) {
        float d = cand_d[base + t]; int i = cand_i[base + t];
        if (d < bdv || (d == bdv && i < biv)) { bdv = d; biv = i; }
    }
    gidx[p] = biv;
    out[IDX_OFF + p] = (float)biv;
}

// ---------------------------------------------------------------------------
// gather quantized output + loss partials   (proven R4 body)
// ---------------------------------------------------------------------------
__global__ void __launch_bounds__(256)
k_out(const float* __restrict__ in, const float* __restrict__ cb,
      const int* __restrict__ gidx, float* __restrict__ out,
      double* __restrict__ partial) {
    __shared__ int idxs[128];
    __shared__ double red[256];
    const int tid = threadIdx.x;
    const int blk = blockIdx.x;
    const int b = blk >> 5, hw0 = (blk & 31) << 7;

    if (tid < 128) idxs[tid] = gidx[(b << 12) + hw0 + tid];
    __syncthreads();

    const float* inb  = in  + ((size_t)b << 20);
    float*       outb = out + ((size_t)b << 20);

    double acc = 0.0;
    for (int t = tid; t < CDIM * 128; t += 256) {
        int d = t >> 7, p = t & 127;
        float q = cb[(size_t)idxs[p] * CDIM + d];
        float x = inb[(size_t)d * HW + hw0 + p];
        outb[(size_t)d * HW + hw0 + p] = q;
        float df = q - x;
        acc += (double)df * (double)df;
    }

    red[tid] = acc;
    __syncthreads();
    #pragma unroll
    for (int s = 128; s > 0; s >>= 1) {
        if (tid < s) red[tid] += red[tid + s];
        __syncthreads();
    }
    if (tid == 0) partial[blk] = red[0];
}

__global__ void k_final(const double* __restrict__ partial, float* __restrict__ out) {
    __shared__ double red[256];
    int tid = threadIdx.x;
    double a = 0.0;
    for (int t = tid; t < NTILES; t += 256) a += partial[t];
    red[tid] = a;
    __syncthreads();
    #pragma unroll
    for (int s = 128; s > 0; s >>= 1) {
        if (tid < s) red[tid] += red[tid + s];
        __syncthreads();
    }
    if (tid == 0) {
        double mse = red[0] / (double)(NPIX * (double)CDIM);
        out[LOSS_OFF] = (float)(1.25 * mse);
    }
}

// ---------------------------------------------------------------------------
extern "C" void kernel_launch(void* const* d_in, const int* in_sizes, int n_in,
                              void* d_out, int out_size) {
    (void)in_sizes; (void)n_in; (void)out_size;
    const float* in = (const float*)d_in[0];
    const float* cb = (const float*)d_in[1];
    float* out = (float*)d_out;

    __half* A_p; __half* B_p;
    float *s1_p, *s2_p, *cd_p; int *ci_p, *idx_p; double* part_p;
    cudaGetSymbolAddress((void**)&A_p,   g_A);
    cudaGetSymbolAddress((void**)&B_p,   g_B);
    cudaGetSymbolAddress((void**)&s1_p,  g_s1);
    cudaGetSymbolAddress((void**)&s2_p,  g_s2);
    cudaGetSymbolAddress((void**)&cd_p,  g_cand_d);
    cudaGetSymbolAddress((void**)&ci_p,  g_cand_i);
    cudaGetSymbolAddress((void**)&idx_p, g_idx);
    cudaGetSymbolAddress((void**)&part_p, g_partial);

    const int smem_a = 256 * 69 * 4;             // 70656
    const int smem_g = 4096 + 3 * 32768;         // 102400
    cudaFuncSetAttribute(k_split_a, cudaFuncAttributeMaxDynamicSharedMemorySize, smem_a);
    cudaFuncSetAttribute(k_gemm,    cudaFuncAttributeMaxDynamicSharedMemorySize, smem_g);

    k_split_b<<<4, 256>>>(cb, B_p, s2_p);                      // idx 0
    k_split_a<<<1024, 256, smem_a>>>(in, A_p, s1_p);           // idx 1
    k_nop<<<1, 32>>>();                                        // idx 2 (shifts gemm to captured slot)
    k_gemm<<<4096, 128, smem_g>>>(A_p, B_p, s1_p, s2_p, cd_p, ci_p);  // idx 3 -> ncu
    k_combine<<<256, 256>>>(cd_p, ci_p, idx_p, out);           // idx 4
    k_out<<<NTILES, 256>>>(in, cb, idx_p, out, part_p);        // idx 5
    k_final<<<1, 256>>>(part_p, out);                          // idx 6
}

// round 11
// speedup vs baseline: 1.9418x; 1.8212x over previous
#include <cuda_runtime.h>
#include <cuda_fp16.h>
#include <cstdint>

#define CDIM 256
#define HW 4096
#define NPIX 65536
#define NTILES 512
#define KCODES 1024
#define LOSS_OFF 16777216
#define IDX_OFF  16777217

// scratch (__device__ globals; no cudaMalloc allowed)
__device__ __half  g_A[(size_t)NPIX * 512];     // [pixel][xh(256)|xl(256)]   64 MB
__device__ __half  g_B[(size_t)KCODES * 768];   // [code][Eh|Eh|El]           1.5 MB
__device__ float   g_s1[NPIX];
__device__ float   g_s2[KCODES];
__device__ float   g_cand_d[NPIX * 8];
__device__ int     g_cand_i[NPIX * 8];
__device__ int     g_idx[NPIX];
__device__ double  g_partial[NTILES];

__device__ __forceinline__ uint32_t smem_u32(const void* p) {
    uint32_t a;
    asm("{ .reg .u64 t; cvta.to.shared.u64 t, %1; cvt.u32.u64 %0, t; }" : "=r"(a) : "l"(p));
    return a;
}

#define LDSM4(r0, r1, r2, r3, addr) \
    asm volatile("ldmatrix.sync.aligned.m8n8.x4.shared.b16 {%0,%1,%2,%3}, [%4];" \
        : "=r"(r0), "=r"(r1), "=r"(r2), "=r"(r3) : "r"(addr))

#define MMA16816(c0, c1, c2, c3, a0, a1, a2, a3, b0, b1) \
    asm volatile("mma.sync.aligned.m16n8k16.row.col.f32.f16.f16.f32 " \
        "{%0,%1,%2,%3}, {%4,%5,%6,%7}, {%8,%9}, {%0,%1,%2,%3};" \
        : "+f"(c0), "+f"(c1), "+f"(c2), "+f"(c3) \
        : "r"(a0), "r"(a1), "r"(a2), "r"(a3), "r"(b0), "r"(b1))

__global__ void k_nop() {}

// ---------------------------------------------------------------------------
// split codebook: warp-per-code, coalesced. s2 via warp shuffle (reorder safe:
// |delta s2| ~1e-11 << dist ulp 3e-8).
// ---------------------------------------------------------------------------
__global__ void __launch_bounds__(256)
k_split_b(const float* __restrict__ cb, __half* __restrict__ B_,
          float* __restrict__ s2g) {
    const int gw = (blockIdx.x * 256 + threadIdx.x) >> 5;   // global warp = code
    const int l  = threadIdx.x & 31;
    if (gw >= KCODES) return;
    const float* row = cb + (size_t)gw * CDIM;
    __half* o = B_ + (size_t)gw * 768;
    float e[8];
    float s = 0.f;
    #pragma unroll
    for (int j = 0; j < 8; ++j) {
        e[j] = row[l + 32 * j];
        s += e[j] * e[j];
    }
    #pragma unroll
    for (int off = 16; off > 0; off >>= 1)
        s += __shfl_down_sync(0xffffffffu, s, off);
    if (l == 0) s2g[gw] = s;
    #pragma unroll
    for (int j = 0; j < 8; ++j) {
        int d = l + 32 * j;
        float E = e[j] * 1024.0f;
        __half eh = __float2half_rn(E);
        __half el = __float2half_rn(E - __half2float(eh));
        o[d] = eh; o[256 + d] = eh; o[512 + d] = el;
    }
}

// ---------------------------------------------------------------------------
// split inputs -> fp16 hi/lo [pixel][d]; s1 sequential-d   (proven R8)
// (placed at captured launch index 3 this round for profiling)
// ---------------------------------------------------------------------------
__global__ void __launch_bounds__(256)
k_split_a(const float* __restrict__ in, __half* __restrict__ A_,
          float* __restrict__ s1g) {
    extern __shared__ float xs[];   // [256 d][stride 69]
    const int tid = threadIdx.x;
    const int blk = blockIdx.x;                 // 1024 blocks of 64 pixels
    const int b = blk >> 6, hw0 = (blk & 63) << 6;
    const float* inb = in + ((size_t)b << 20);

    for (int t = tid; t < 256 * 16; t += 256) {
        int d = t >> 4, p4 = t & 15;
        float4 v = *(const float4*)(inb + (size_t)d * HW + hw0 + p4 * 4);
        float* dst = xs + d * 69 + p4 * 4;
        dst[0] = v.x; dst[1] = v.y; dst[2] = v.z; dst[3] = v.w;
    }
    __syncthreads();

    if (tid < 64) {
        float s = 0.f;
        for (int d = 0; d < CDIM; ++d) { float v = xs[d * 69 + tid]; s += v * v; }
        s1g[blk * 64 + tid] = s;
    }

    const int d = tid;
    for (int i = 0; i < 64; ++i) {
        float x = xs[d * 69 + i];
        __half xh = __float2half_rn(x);
        __half xl = __float2half_rn(x - __half2float(xh));
        size_t row = ((size_t)(blk * 64 + i)) << 9;   // *512
        A_[row + d] = xh;
        A_[row + 256 + d] = xl;
    }
}

// ---------------------------------------------------------------------------
// HMMA GEMM tile (proven R10 body): 128 px x 128 codes; 4 warps, 64x64 warp
// tile; 3-stage XOR-swizzled pipeline, ONE __syncthreads per chunk.
// ---------------------------------------------------------------------------
__device__ __forceinline__ void load_chunk3(uint32_t st, const char* Ag, const char* Bg,
                                            int p0, int nt, int kc, int tid) {
    const size_t aoff = (size_t)(kc & 7) * 128;
    const size_t boff = (size_t)kc * 128;
    #pragma unroll
    for (int i = 0; i < 8; ++i) {
        int o = tid + 128 * i;           // 0..1023
        int row = o >> 3, seg = (o & 7) * 16;
        const char* src = Ag + ((size_t)(p0 + row) << 10) + aoff + seg;
        uint32_t dst = st + row * 128 + (seg ^ ((row & 7) << 4));
        asm volatile("cp.async.cg.shared.global [%0], [%1], 16;" :: "r"(dst), "l"(src));
    }
    #pragma unroll
    for (int i = 0; i < 8; ++i) {
        int o = tid + 128 * i;
        int row = o >> 3, seg = (o & 7) * 16;
        const char* src = Bg + (size_t)(nt * 128 + row) * 1536 + boff + seg;
        uint32_t dst = st + 16384 + row * 128 + (seg ^ ((row & 7) << 4));
        asm volatile("cp.async.cg.shared.global [%0], [%1], 16;" :: "r"(dst), "l"(src));
    }
}

__global__ void __launch_bounds__(128, 2)
k_gemm(const __half* __restrict__ Ah, const __half* __restrict__ Bh,
       const float* __restrict__ s1g, const float* __restrict__ s2g,
       float* __restrict__ cand_d, int* __restrict__ cand_i) {
    extern __shared__ char sm[];
    uint32_t sb = smem_u32(sm);
    float* rd = (float*)sm;
    int*   ri = (int*)(sm + 1024);
    float* s2s = (float*)(sm + 2048);
    const uint32_t stg = sb + 4096;

    const int tid = threadIdx.x, lane = tid & 31, wid = tid >> 5;
    const int warp_m = wid & 1, warp_n = wid >> 1;    // 2M x 2N warp grid
    const int m0 = warp_m * 64, n0 = warp_n * 64;
    const int blk = blockIdx.x, pb = blk >> 3, nt = blk & 7;   // 8 code tiles
    const int p0 = pb * 128;
    const char* Ag = (const char*)Ah;
    const char* Bg = (const char*)Bh;

    s2s[tid] = s2g[nt * 128 + tid];

    const int rA = (lane & 7) + ((lane >> 3) & 1) * 8;
    const int cA = (lane >> 4) * 16;
    const int mA = (rA & 7) << 4;
    uint32_t arow[4];
    #pragma unroll
    for (int f = 0; f < 4; ++f) arow[f] = (uint32_t)(m0 + f * 16 + rA) * 128;
    const int rB = (lane & 7) + ((lane >> 4) << 3);
    const int cB = ((lane >> 3) & 1) * 16;
    const int mB = (rB & 7) << 4;
    uint32_t brow[4];
    #pragma unroll
    for (int g = 0; g < 4; ++g) brow[g] = (uint32_t)(n0 + g * 16 + rB) * 128;

    float s1v[8];
    #pragma unroll
    for (int s = 0; s < 8; ++s)
        s1v[s] = s1g[p0 + m0 + (s >> 1) * 16 + (lane >> 2) + (s & 1) * 8];

    float c[4][8][4];
    #pragma unroll
    for (int mf = 0; mf < 4; ++mf)
        #pragma unroll
        for (int j = 0; j < 8; ++j)
            #pragma unroll
            for (int q = 0; q < 4; ++q) c[mf][j][q] = 0.f;

    load_chunk3(stg,         Ag, Bg, p0, nt, 0, tid);
    asm volatile("cp.async.commit_group;" ::: "memory");
    load_chunk3(stg + 32768, Ag, Bg, p0, nt, 1, tid);
    asm volatile("cp.async.commit_group;" ::: "memory");

    for (int kc = 0; kc < 12; ++kc) {
        if (kc < 11) asm volatile("cp.async.wait_group 1;" ::: "memory");
        else         asm volatile("cp.async.wait_group 0;" ::: "memory");
        __syncthreads();
        if (kc + 2 < 12) {
            load_chunk3(stg + ((kc + 2) % 3) * 32768, Ag, Bg, p0, nt, kc + 2, tid);
            asm volatile("cp.async.commit_group;" ::: "memory");
        }

        const uint32_t sA = stg + (kc % 3) * 32768;
        const uint32_t sB = sA + 16384;
        #pragma unroll
        for (int ks = 0; ks < 4; ++ks) {
            const uint32_t colA = (uint32_t)((cA + ks * 32) ^ mA);
            const uint32_t colB = (uint32_t)((cB + ks * 32) ^ mB);
            uint32_t a[4][4], bf[4][4];
            #pragma unroll
            for (int f = 0; f < 4; ++f)
                LDSM4(a[f][0], a[f][1], a[f][2], a[f][3], sA + arow[f] + colA);
            #pragma unroll
            for (int g = 0; g < 4; ++g)
                LDSM4(bf[g][0], bf[g][1], bf[g][2], bf[g][3], sB + brow[g] + colB);

            #pragma unroll
            for (int f = 0; f < 4; ++f) {
                #pragma unroll
                for (int g = 0; g < 4; ++g) {
                    MMA16816(c[f][2*g][0], c[f][2*g][1], c[f][2*g][2], c[f][2*g][3],
                             a[f][0], a[f][1], a[f][2], a[f][3], bf[g][0], bf[g][1]);
                    MMA16816(c[f][2*g+1][0], c[f][2*g+1][1], c[f][2*g+1][2], c[f][2*g+1][3],
                             a[f][0], a[f][1], a[f][2], a[f][3], bf[g][2], bf[g][3]);
                }
            }
        }
    }

    const float SC = 0.001953125f;   // 2^-9
    float bd[8];
    int   bi[8];
    #pragma unroll
    for (int s = 0; s < 8; ++s) { bd[s] = 3.4e38f; bi[s] = 0; }
    #pragma unroll
    for (int mf = 0; mf < 4; ++mf) {
        #pragma unroll
        for (int j = 0; j < 8; ++j) {
            const int nl = n0 + j * 8 + ((lane & 3) << 1);
            const float s2a = s2s[nl], s2b = s2s[nl + 1];
            const int sl0 = mf * 2, sl1 = mf * 2 + 1;
            float d0 = (s1v[sl0] + s2a) - c[mf][j][0] * SC;
            float d1 = (s1v[sl0] + s2b) - c[mf][j][1] * SC;
            float d2 = (s1v[sl1] + s2a) - c[mf][j][2] * SC;
            float d3 = (s1v[sl1] + s2b) - c[mf][j][3] * SC;
            if (d0 < bd[sl0]) { bd[sl0] = d0; bi[sl0] = nl; }
            if (d1 < bd[sl0]) { bd[sl0] = d1; bi[sl0] = nl + 1; }
            if (d2 < bd[sl1]) { bd[sl1] = d2; bi[sl1] = nl; }
            if (d3 < bd[sl1]) { bd[sl1] = d3; bi[sl1] = nl + 1; }
        }
    }
    #pragma unroll
    for (int s = 0; s < 8; ++s) {
        #pragma unroll
        for (int off = 1; off <= 2; off <<= 1) {
            float od = __shfl_xor_sync(0xffffffffu, bd[s], off);
            int   oi = __shfl_xor_sync(0xffffffffu, bi[s], off);
            if (od < bd[s] || (od == bd[s] && oi < bi[s])) { bd[s] = od; bi[s] = oi; }
        }
    }
    __syncthreads();
    if ((lane & 3) == 0) {
        #pragma unroll
        for (int s = 0; s < 8; ++s) {
            int row = m0 + (s >> 1) * 16 + (lane >> 2) + (s & 1) * 8;
            rd[row * 2 + warp_n] = bd[s];
            ri[row * 2 + warp_n] = bi[s];
        }
    }
    __syncthreads();
    {
        float d0 = rd[tid * 2], d1 = rd[tid * 2 + 1];
        int i0 = ri[tid * 2], i1 = ri[tid * 2 + 1];
        bool t1 = (d1 < d0 || (d1 == d0 && i1 < i0));
        cand_d[(size_t)(p0 + tid) * 8 + nt] = t1 ? d1 : d0;
        cand_i[(size_t)(p0 + tid) * 8 + nt] = nt * 128 + (t1 ? i1 : i0);
    }
}

// ---------------------------------------------------------------------------
// combine 8 candidates -> index; ALSO reduce best-dist into loss partials
// (loss = 1.25 * mean(dist_best); deterministic double tree)
// ---------------------------------------------------------------------------
__global__ void __launch_bounds__(256)
k_combine(const float* __restrict__ cand_d, const int* __restrict__ cand_i,
          int* __restrict__ gidx, float* __restrict__ out,
          double* __restrict__ partial) {
    __shared__ double red[256];
    const int tid = threadIdx.x;
    const int p = blockIdx.x * 256 + tid;
    size_t base = (size_t)p * 8;
    float bdv = cand_d[base]; int biv = cand_i[base];
    #pragma unroll
    for (int t = 1; t < 8; ++t) {
        float d = cand_d[base + t]; int i = cand_i[base + t];
        if (d < bdv || (d == bdv && i < biv)) { bdv = d; biv = i; }
    }
    gidx[p] = biv;
    out[IDX_OFF + p] = (float)biv;

    red[tid] = (double)bdv;
    __syncthreads();
    #pragma unroll
    for (int s = 128; s > 0; s >>= 1) {
        if (tid < s) red[tid] += red[tid + s];
        __syncthreads();
    }
    if (tid == 0) partial[blockIdx.x] = red[0];
}

// ---------------------------------------------------------------------------
// gather quantized output only (no input read, no loss)
// ---------------------------------------------------------------------------
__global__ void __launch_bounds__(256)
k_out(const float* __restrict__ cb, const int* __restrict__ gidx,
      float* __restrict__ out) {
    __shared__ int idxs[128];
    const int tid = threadIdx.x;
    const int blk = blockIdx.x;
    const int b = blk >> 5, hw0 = (blk & 31) << 7;

    if (tid < 128) idxs[tid] = gidx[(b << 12) + hw0 + tid];
    __syncthreads();

    float* outb = out + ((size_t)b << 20);
    for (int t = tid; t < CDIM * 128; t += 256) {
        int d = t >> 7, p = t & 127;
        outb[(size_t)d * HW + hw0 + p] = cb[(size_t)idxs[p] * CDIM + d];
    }
}

__global__ void k_final(const double* __restrict__ partial, float* __restrict__ out) {
    __shared__ double red[256];
    int tid = threadIdx.x;
    red[tid] = partial[tid];   // 256 partials, one per combine block
    __syncthreads();
    #pragma unroll
    for (int s = 128; s > 0; s >>= 1) {
        if (tid < s) red[tid] += red[tid + s];
        __syncthreads();
    }
    if (tid == 0) {
        double mse = red[0] / ((double)NPIX * (double)CDIM);
        out[LOSS_OFF] = (float)(1.25 * mse);
    }
}

// ---------------------------------------------------------------------------
extern "C" void kernel_launch(void* const* d_in, const int* in_sizes, int n_in,
                              void* d_out, int out_size) {
    (void)in_sizes; (void)n_in; (void)out_size;
    const float* in = (const float*)d_in[0];
    const float* cb = (const float*)d_in[1];
    float* out = (float*)d_out;

    __half* A_p; __half* B_p;
    float *s1_p, *s2_p, *cd_p; int *ci_p, *idx_p; double* part_p;
    cudaGetSymbolAddress((void**)&A_p,   g_A);
    cudaGetSymbolAddress((void**)&B_p,   g_B);
    cudaGetSymbolAddress((void**)&s1_p,  g_s1);
    cudaGetSymbolAddress((void**)&s2_p,  g_s2);
    cudaGetSymbolAddress((void**)&cd_p,  g_cand_d);
    cudaGetSymbolAddress((void**)&ci_p,  g_cand_i);
    cudaGetSymbolAddress((void**)&idx_p, g_idx);
    cudaGetSymbolAddress((void**)&part_p, g_partial);

    const int smem_a = 256 * 69 * 4;             // 70656
    const int smem_g = 4096 + 3 * 32768;         // 102400
    cudaFuncSetAttribute(k_split_a, cudaFuncAttributeMaxDynamicSharedMemorySize, smem_a);
    cudaFuncSetAttribute(k_gemm,    cudaFuncAttributeMaxDynamicSharedMemorySize, smem_g);

    k_split_b<<<128, 256>>>(cb, B_p, s2_p);                    // idx 0
    k_nop<<<1, 32>>>();                                        // idx 1
    k_nop<<<1, 32>>>();                                        // idx 2
    k_split_a<<<1024, 256, smem_a>>>(in, A_p, s1_p);           // idx 3 -> ncu
    k_gemm<<<4096, 128, smem_g>>>(A_p, B_p, s1_p, s2_p, cd_p, ci_p);  // idx 4
    k_combine<<<256, 256>>>(cd_p, ci_p, idx_p, out, part_p);   // idx 5
    k_out<<<NTILES, 256>>>(cb, idx_p, out);                    // idx 6
    k_final<<<1, 256>>>(part_p, out);                          // idx 7
}

// round 12
// speedup vs baseline: 1.9693x; 1.0142x over previous
#include <cuda_runtime.h>
#include <cuda_fp16.h>
#include <cstdint>

#define CDIM 256
#define HW 4096
#define NPIX 65536
#define NTILES 512
#define KCODES 1024
#define LOSS_OFF 16777216
#define IDX_OFF  16777217

// scratch (__device__ globals; no cudaMalloc allowed)
__device__ __half  g_A[(size_t)NPIX * 512];     // [pixel][xh(256)|xl(256)]   64 MB
__device__ __half  g_B[(size_t)KCODES * 768];   // [code][Eh|Eh|El]           1.5 MB
__device__ float   g_s1[NPIX];
__device__ float   g_s2[KCODES];
__device__ float   g_cand_d[NPIX * 8];
__device__ int     g_cand_i[NPIX * 8];
__device__ double  g_partial[NTILES];

__device__ __forceinline__ uint32_t smem_u32(const void* p) {
    uint32_t a;
    asm("{ .reg .u64 t; cvta.to.shared.u64 t, %1; cvt.u32.u64 %0, t; }" : "=r"(a) : "l"(p));
    return a;
}

#define LDSM4(r0, r1, r2, r3, addr) \
    asm volatile("ldmatrix.sync.aligned.m8n8.x4.shared.b16 {%0,%1,%2,%3}, [%4];" \
        : "=r"(r0), "=r"(r1), "=r"(r2), "=r"(r3) : "r"(addr))

#define MMA16816(c0, c1, c2, c3, a0, a1, a2, a3, b0, b1) \
    asm volatile("mma.sync.aligned.m16n8k16.row.col.f32.f16.f16.f32 " \
        "{%0,%1,%2,%3}, {%4,%5,%6,%7}, {%8,%9}, {%0,%1,%2,%3};" \
        : "+f"(c0), "+f"(c1), "+f"(c2), "+f"(c3) \
        : "r"(a0), "r"(a1), "r"(a2), "r"(a3), "r"(b0), "r"(b1))

// ---------------------------------------------------------------------------
// split codebook: warp-per-code, coalesced   (proven R11)
// ---------------------------------------------------------------------------
__global__ void __launch_bounds__(256)
k_split_b(const float* __restrict__ cb, __half* __restrict__ B_,
          float* __restrict__ s2g) {
    const int gw = (blockIdx.x * 256 + threadIdx.x) >> 5;   // global warp = code
    const int l  = threadIdx.x & 31;
    if (gw >= KCODES) return;
    const float* row = cb + (size_t)gw * CDIM;
    __half* o = B_ + (size_t)gw * 768;
    float e[8];
    float s = 0.f;
    #pragma unroll
    for (int j = 0; j < 8; ++j) {
        e[j] = row[l + 32 * j];
        s += e[j] * e[j];
    }
    #pragma unroll
    for (int off = 16; off > 0; off >>= 1)
        s += __shfl_down_sync(0xffffffffu, s, off);
    if (l == 0) s2g[gw] = s;
    #pragma unroll
    for (int j = 0; j < 8; ++j) {
        int d = l + 32 * j;
        float E = e[j] * 1024.0f;
        __half eh = __float2half_rn(E);
        __half el = __float2half_rn(E - __half2float(eh));
        o[d] = eh; o[256 + d] = eh; o[512 + d] = el;
    }
}

// ---------------------------------------------------------------------------
// split inputs -> fp16 hi/lo [pixel][d]; s1 sequential-d (bit-identical).
// Store phase: thread owns channel pair (2t, 2t+1) -> coalesced half2 stores.
// ---------------------------------------------------------------------------
__global__ void __launch_bounds__(256)
k_split_a(const float* __restrict__ in, __half* __restrict__ A_,
          float* __restrict__ s1g) {
    extern __shared__ float xs[];   // [256 d][stride 69]
    const int tid = threadIdx.x;
    const int blk = blockIdx.x;                 // 1024 blocks of 64 pixels
    const int b = blk >> 6, hw0 = (blk & 63) << 6;
    const float* inb = in + ((size_t)b << 20);

    for (int t = tid; t < 256 * 16; t += 256) {
        int d = t >> 4, p4 = t & 15;
        float4 v = *(const float4*)(inb + (size_t)d * HW + hw0 + p4 * 4);
        float* dst = xs + d * 69 + p4 * 4;
        dst[0] = v.x; dst[1] = v.y; dst[2] = v.z; dst[3] = v.w;
    }
    __syncthreads();

    if (tid < 64) {   // sequential-d order -> bit-identical s1
        float s = 0.f;
        for (int d = 0; d < CDIM; ++d) { float v = xs[d * 69 + tid]; s += v * v; }
        s1g[blk * 64 + tid] = s;
    }

    // channel-pair split: h = i-half, t = channel pair
    const int h = tid >> 7, t = tid & 127;
    const int d0 = 2 * t;
    for (int i = 32 * h; i < 32 * h + 32; ++i) {
        float x0 = xs[d0 * 69 + i];
        float x1 = xs[(d0 + 1) * 69 + i];
        __half xh0 = __float2half_rn(x0);
        __half xh1 = __float2half_rn(x1);
        __half xl0 = __float2half_rn(x0 - __half2float(xh0));
        __half xl1 = __float2half_rn(x1 - __half2float(xh1));
        size_t row = ((size_t)(blk * 64 + i)) << 9;   // *512
        *(__half2*)(A_ + row + d0)       = __halves2half2(xh0, xh1);
        *(__half2*)(A_ + row + 256 + d0) = __halves2half2(xl0, xl1);
    }
}

// ---------------------------------------------------------------------------
// HMMA GEMM tile (proven R10 body): 128 px x 128 codes; 4 warps, 64x64 warp
// tile; 3-stage XOR-swizzled pipeline, ONE __syncthreads per chunk.
// ---------------------------------------------------------------------------
__device__ __forceinline__ void load_chunk3(uint32_t st, const char* Ag, const char* Bg,
                                            int p0, int nt, int kc, int tid) {
    const size_t aoff = (size_t)(kc & 7) * 128;
    const size_t boff = (size_t)kc * 128;
    #pragma unroll
    for (int i = 0; i < 8; ++i) {
        int o = tid + 128 * i;           // 0..1023
        int row = o >> 3, seg = (o & 7) * 16;
        const char* src = Ag + ((size_t)(p0 + row) << 10) + aoff + seg;
        uint32_t dst = st + row * 128 + (seg ^ ((row & 7) << 4));
        asm volatile("cp.async.cg.shared.global [%0], [%1], 16;" :: "r"(dst), "l"(src));
    }
    #pragma unroll
    for (int i = 0; i < 8; ++i) {
        int o = tid + 128 * i;
        int row = o >> 3, seg = (o & 7) * 16;
        const char* src = Bg + (size_t)(nt * 128 + row) * 1536 + boff + seg;
        uint32_t dst = st + 16384 + row * 128 + (seg ^ ((row & 7) << 4));
        asm volatile("cp.async.cg.shared.global [%0], [%1], 16;" :: "r"(dst), "l"(src));
    }
}

__global__ void __launch_bounds__(128, 2)
k_gemm(const __half* __restrict__ Ah, const __half* __restrict__ Bh,
       const float* __restrict__ s1g, const float* __restrict__ s2g,
       float* __restrict__ cand_d, int* __restrict__ cand_i) {
    extern __shared__ char sm[];
    uint32_t sb = smem_u32(sm);
    float* rd = (float*)sm;
    int*   ri = (int*)(sm + 1024);
    float* s2s = (float*)(sm + 2048);
    const uint32_t stg = sb + 4096;

    const int tid = threadIdx.x, lane = tid & 31, wid = tid >> 5;
    const int warp_m = wid & 1, warp_n = wid >> 1;    // 2M x 2N warp grid
    const int m0 = warp_m * 64, n0 = warp_n * 64;
    const int blk = blockIdx.x, pb = blk >> 3, nt = blk & 7;   // 8 code tiles
    const int p0 = pb * 128;
    const char* Ag = (const char*)Ah;
    const char* Bg = (const char*)Bh;

    s2s[tid] = s2g[nt * 128 + tid];

    const int rA = (lane & 7) + ((lane >> 3) & 1) * 8;
    const int cA = (lane >> 4) * 16;
    const int mA = (rA & 7) << 4;
    uint32_t arow[4];
    #pragma unroll
    for (int f = 0; f < 4; ++f) arow[f] = (uint32_t)(m0 + f * 16 + rA) * 128;
    const int rB = (lane & 7) + ((lane >> 4) << 3);
    const int cB = ((lane >> 3) & 1) * 16;
    const int mB = (rB & 7) << 4;
    uint32_t brow[4];
    #pragma unroll
    for (int g = 0; g < 4; ++g) brow[g] = (uint32_t)(n0 + g * 16 + rB) * 128;

    float s1v[8];
    #pragma unroll
    for (int s = 0; s < 8; ++s)
        s1v[s] = s1g[p0 + m0 + (s >> 1) * 16 + (lane >> 2) + (s & 1) * 8];

    float c[4][8][4];
    #pragma unroll
    for (int mf = 0; mf < 4; ++mf)
        #pragma unroll
        for (int j = 0; j < 8; ++j)
            #pragma unroll
            for (int q = 0; q < 4; ++q) c[mf][j][q] = 0.f;

    load_chunk3(stg,         Ag, Bg, p0, nt, 0, tid);
    asm volatile("cp.async.commit_group;" ::: "memory");
    load_chunk3(stg + 32768, Ag, Bg, p0, nt, 1, tid);
    asm volatile("cp.async.commit_group;" ::: "memory");

    for (int kc = 0; kc < 12; ++kc) {
        if (kc < 11) asm volatile("cp.async.wait_group 1;" ::: "memory");
        else         asm volatile("cp.async.wait_group 0;" ::: "memory");
        __syncthreads();
        if (kc + 2 < 12) {
            load_chunk3(stg + ((kc + 2) % 3) * 32768, Ag, Bg, p0, nt, kc + 2, tid);
            asm volatile("cp.async.commit_group;" ::: "memory");
        }

        const uint32_t sA = stg + (kc % 3) * 32768;
        const uint32_t sB = sA + 16384;
        #pragma unroll
        for (int ks = 0; ks < 4; ++ks) {
            const uint32_t colA = (uint32_t)((cA + ks * 32) ^ mA);
            const uint32_t colB = (uint32_t)((cB + ks * 32) ^ mB);
            uint32_t a[4][4], bf[4][4];
            #pragma unroll
            for (int f = 0; f < 4; ++f)
                LDSM4(a[f][0], a[f][1], a[f][2], a[f][3], sA + arow[f] + colA);
            #pragma unroll
            for (int g = 0; g < 4; ++g)
                LDSM4(bf[g][0], bf[g][1], bf[g][2], bf[g][3], sB + brow[g] + colB);

            #pragma unroll
            for (int f = 0; f < 4; ++f) {
                #pragma unroll
                for (int g = 0; g < 4; ++g) {
                    MMA16816(c[f][2*g][0], c[f][2*g][1], c[f][2*g][2], c[f][2*g][3],
                             a[f][0], a[f][1], a[f][2], a[f][3], bf[g][0], bf[g][1]);
                    MMA16816(c[f][2*g+1][0], c[f][2*g+1][1], c[f][2*g+1][2], c[f][2*g+1][3],
                             a[f][0], a[f][1], a[f][2], a[f][3], bf[g][2], bf[g][3]);
                }
            }
        }
    }

    const float SC = 0.001953125f;   // 2^-9
    float bd[8];
    int   bi[8];
    #pragma unroll
    for (int s = 0; s < 8; ++s) { bd[s] = 3.4e38f; bi[s] = 0; }
    #pragma unroll
    for (int mf = 0; mf < 4; ++mf) {
        #pragma unroll
        for (int j = 0; j < 8; ++j) {
            const int nl = n0 + j * 8 + ((lane & 3) << 1);
            const float s2a = s2s[nl], s2b = s2s[nl + 1];
            const int sl0 = mf * 2, sl1 = mf * 2 + 1;
            float d0 = (s1v[sl0] + s2a) - c[mf][j][0] * SC;
            float d1 = (s1v[sl0] + s2b) - c[mf][j][1] * SC;
            float d2 = (s1v[sl1] + s2a) - c[mf][j][2] * SC;
            float d3 = (s1v[sl1] + s2b) - c[mf][j][3] * SC;
            if (d0 < bd[sl0]) { bd[sl0] = d0; bi[sl0] = nl; }
            if (d1 < bd[sl0]) { bd[sl0] = d1; bi[sl0] = nl + 1; }
            if (d2 < bd[sl1]) { bd[sl1] = d2; bi[sl1] = nl; }
            if (d3 < bd[sl1]) { bd[sl1] = d3; bi[sl1] = nl + 1; }
        }
    }
    #pragma unroll
    for (int s = 0; s < 8; ++s) {
        #pragma unroll
        for (int off = 1; off <= 2; off <<= 1) {
            float od = __shfl_xor_sync(0xffffffffu, bd[s], off);
            int   oi = __shfl_xor_sync(0xffffffffu, bi[s], off);
            if (od < bd[s] || (od == bd[s] && oi < bi[s])) { bd[s] = od; bi[s] = oi; }
        }
    }
    __syncthreads();
    if ((lane & 3) == 0) {
        #pragma unroll
        for (int s = 0; s < 8; ++s) {
            int row = m0 + (s >> 1) * 16 + (lane >> 2) + (s & 1) * 8;
            rd[row * 2 + warp_n] = bd[s];
            ri[row * 2 + warp_n] = bi[s];
        }
    }
    __syncthreads();
    {
        float d0 = rd[tid * 2], d1 = rd[tid * 2 + 1];
        int i0 = ri[tid * 2], i1 = ri[tid * 2 + 1];
        bool t1 = (d1 < d0 || (d1 == d0 && i1 < i0));
        cand_d[(size_t)(p0 + tid) * 8 + nt] = t1 ? d1 : d0;
        cand_i[(size_t)(p0 + tid) * 8 + nt] = nt * 128 + (t1 ? i1 : i0);
    }
}

// ---------------------------------------------------------------------------
// fused: combine 8 candidates -> index + loss partial + float4 gather output
// smem: idxs[128] | sd[128] | red[256] dbl
// ---------------------------------------------------------------------------
__global__ void __launch_bounds__(256)
k_out(const float* __restrict__ cb,
      const float* __restrict__ cand_d, const int* __restrict__ cand_i,
      float* __restrict__ out, double* __restrict__ partial) {
    __shared__ int idxs[128];
    __shared__ float sd[128];
    __shared__ double red[256];
    const int tid = threadIdx.x;
    const int blk = blockIdx.x;
    const int b = blk >> 5, hw0 = (blk & 31) << 7;

    if (tid < 128) {
        const int pp = blk * 128 + tid;   // flat pixel index
        size_t base = (size_t)pp * 8;
        float bdv = cand_d[base]; int biv = cand_i[base];
        #pragma unroll
        for (int t = 1; t < 8; ++t) {
            float d = cand_d[base + t]; int i = cand_i[base + t];
            if (d < bdv || (d == bdv && i < biv)) { bdv = d; biv = i; }
        }
        idxs[tid] = biv;
        sd[tid] = bdv;
        out[IDX_OFF + pp] = (float)biv;
    }
    __syncthreads();

    // loss partial (deterministic double tree over this block's 128 pixels)
    red[tid] = (tid < 128) ? (double)sd[tid] : 0.0;
    __syncthreads();
    #pragma unroll
    for (int s = 128; s > 0; s >>= 1) {
        if (tid < s) red[tid] += red[tid + s];
        __syncthreads();
    }
    if (tid == 0) partial[blk] = red[0];

    // gather quantized output: float4 stores (4 pixels per store)
    float* outb = out + ((size_t)b << 20);
    for (int t = tid; t < 256 * 32; t += 256) {
        int d = t >> 5, p4 = t & 31;
        float4 v;
        v.x = cb[(size_t)idxs[4 * p4 + 0] * CDIM + d];
        v.y = cb[(size_t)idxs[4 * p4 + 1] * CDIM + d];
        v.z = cb[(size_t)idxs[4 * p4 + 2] * CDIM + d];
        v.w = cb[(size_t)idxs[4 * p4 + 3] * CDIM + d];
        *(float4*)(outb + (size_t)d * HW + hw0 + 4 * p4) = v;
    }
}

__global__ void k_final(const double* __restrict__ partial, float* __restrict__ out) {
    __shared__ double red[256];
    int tid = threadIdx.x;
    red[tid] = partial[tid] + partial[tid + 256];
    __syncthreads();
    #pragma unroll
    for (int s = 128; s > 0; s >>= 1) {
        if (tid < s) red[tid] += red[tid + s];
        __syncthreads();
    }
    if (tid == 0) {
        double mse = red[0] / ((double)NPIX * (double)CDIM);
        out[LOSS_OFF] = (float)(1.25 * mse);
    }
}

// ---------------------------------------------------------------------------
extern "C" void kernel_launch(void* const* d_in, const int* in_sizes, int n_in,
                              void* d_out, int out_size) {
    (void)in_sizes; (void)n_in; (void)out_size;
    const float* in = (const float*)d_in[0];
    const float* cb = (const float*)d_in[1];
    float* out = (float*)d_out;

    __half* A_p; __half* B_p;
    float *s1_p, *s2_p, *cd_p; int* ci_p; double* part_p;
    cudaGetSymbolAddress((void**)&A_p,   g_A);
    cudaGetSymbolAddress((void**)&B_p,   g_B);
    cudaGetSymbolAddress((void**)&s1_p,  g_s1);
    cudaGetSymbolAddress((void**)&s2_p,  g_s2);
    cudaGetSymbolAddress((void**)&cd_p,  g_cand_d);
    cudaGetSymbolAddress((void**)&ci_p,  g_cand_i);
    cudaGetSymbolAddress((void**)&part_p, g_partial);

    const int smem_a = 256 * 69 * 4;             // 70656
    const int smem_g = 4096 + 3 * 32768;         // 102400
    cudaFuncSetAttribute(k_split_a, cudaFuncAttributeMaxDynamicSharedMemorySize, smem_a);
    cudaFuncSetAttribute(k_gemm,    cudaFuncAttributeMaxDynamicSharedMemorySize, smem_g);

    k_split_b<<<128, 256>>>(cb, B_p, s2_p);                           // idx 0
    k_split_a<<<1024, 256, smem_a>>>(in, A_p, s1_p);                  // idx 1
    k_gemm<<<4096, 128, smem_g>>>(A_p, B_p, s1_p, s2_p, cd_p, ci_p);  // idx 2
    k_out<<<NTILES, 256>>>(cb, cd_p, ci_p, out, part_p);              // idx 3 -> ncu
    k_final<<<1, 256>>>(part_p, out);                                 // idx 4
}

// round 13
// speedup vs baseline: 2.3865x; 1.2118x over previous
#include <cuda_runtime.h>
#include <cuda_fp16.h>
#include <cstdint>

#define CDIM 256
#define HW 4096
#define NPIX 65536
#define NTILES 512
#define KCODES 1024
#define LOSS_OFF 16777216
#define IDX_OFF  16777217

// scratch (__device__ globals; no cudaMalloc allowed)
__device__ __half  g_A[(size_t)NPIX * 512];     // [pixel][xh(256)|xl(256)]   64 MB
__device__ __half  g_B[(size_t)KCODES * 768];   // [code][Eh|Eh|El]           1.5 MB
__device__ float   g_s1[NPIX];
__device__ float   g_s2[KCODES];
__device__ float   g_cand_d[NPIX * 8];
__device__ int     g_cand_i[NPIX * 8];
__device__ double  g_partial[NTILES];

__device__ __forceinline__ uint32_t smem_u32(const void* p) {
    uint32_t a;
    asm("{ .reg .u64 t; cvta.to.shared.u64 t, %1; cvt.u32.u64 %0, t; }" : "=r"(a) : "l"(p));
    return a;
}

#define LDSM4(r0, r1, r2, r3, addr) \
    asm volatile("ldmatrix.sync.aligned.m8n8.x4.shared.b16 {%0,%1,%2,%3}, [%4];" \
        : "=r"(r0), "=r"(r1), "=r"(r2), "=r"(r3) : "r"(addr))

#define MMA16816(c0, c1, c2, c3, a0, a1, a2, a3, b0, b1) \
    asm volatile("mma.sync.aligned.m16n8k16.row.col.f32.f16.f16.f32 " \
        "{%0,%1,%2,%3}, {%4,%5,%6,%7}, {%8,%9}, {%0,%1,%2,%3};" \
        : "+f"(c0), "+f"(c1), "+f"(c2), "+f"(c3) \
        : "r"(a0), "r"(a1), "r"(a2), "r"(a3), "r"(b0), "r"(b1))

// ---------------------------------------------------------------------------
// split codebook: warp-per-code, coalesced   (proven R11)
// ---------------------------------------------------------------------------
__global__ void __launch_bounds__(256)
k_split_b(const float* __restrict__ cb, __half* __restrict__ B_,
          float* __restrict__ s2g) {
    const int gw = (blockIdx.x * 256 + threadIdx.x) >> 5;   // global warp = code
    const int l  = threadIdx.x & 31;
    if (gw >= KCODES) return;
    const float* row = cb + (size_t)gw * CDIM;
    __half* o = B_ + (size_t)gw * 768;
    float e[8];
    float s = 0.f;
    #pragma unroll
    for (int j = 0; j < 8; ++j) {
        e[j] = row[l + 32 * j];
        s += e[j] * e[j];
    }
    #pragma unroll
    for (int off = 16; off > 0; off >>= 1)
        s += __shfl_down_sync(0xffffffffu, s, off);
    if (l == 0) s2g[gw] = s;
    #pragma unroll
    for (int j = 0; j < 8; ++j) {
        int d = l + 32 * j;
        float E = e[j] * 1024.0f;
        __half eh = __float2half_rn(E);
        __half el = __float2half_rn(E - __half2float(eh));
        o[d] = eh; o[256 + d] = eh; o[512 + d] = el;
    }
}

// ---------------------------------------------------------------------------
// split inputs -> fp16 hi/lo [pixel][d]; s1 sequential-d (bit-identical).
// Re-tiled: 32 px/CTA (2048 blocks), smem [256 d][stride 37] = 37.9 KB.
// ---------------------------------------------------------------------------
__global__ void __launch_bounds__(256)
k_split_a(const float* __restrict__ in, __half* __restrict__ A_,
          float* __restrict__ s1g) {
    extern __shared__ float xs[];   // [256 d][stride 37]
    const int tid = threadIdx.x;
    const int blk = blockIdx.x;                 // 2048 blocks of 32 pixels
    const int b = blk >> 7, hw0 = (blk & 127) << 5;
    const float* inb = in + ((size_t)b << 20);

    for (int t = tid; t < 256 * 8; t += 256) {
        int d = t >> 3, p4 = t & 7;
        float4 v = *(const float4*)(inb + (size_t)d * HW + hw0 + p4 * 4);
        float* dst = xs + d * 37 + p4 * 4;
        dst[0] = v.x; dst[1] = v.y; dst[2] = v.z; dst[3] = v.w;
    }
    __syncthreads();

    if (tid < 32) {   // sequential-d order -> bit-identical s1
        float s = 0.f;
        for (int d = 0; d < CDIM; ++d) { float v = xs[d * 37 + tid]; s += v * v; }
        s1g[blk * 32 + tid] = s;
    }

    // channel-pair split: h = i-half, t = channel pair -> coalesced half2 stores
    const int h = tid >> 7, t = tid & 127;
    const int d0 = 2 * t;
    for (int i = 16 * h; i < 16 * h + 16; ++i) {
        float x0 = xs[d0 * 37 + i];
        float x1 = xs[(d0 + 1) * 37 + i];
        __half xh0 = __float2half_rn(x0);
        __half xh1 = __float2half_rn(x1);
        __half xl0 = __float2half_rn(x0 - __half2float(xh0));
        __half xl1 = __float2half_rn(x1 - __half2float(xh1));
        size_t row = ((size_t)(blk * 32 + i)) << 9;   // *512
        *(__half2*)(A_ + row + d0)       = __halves2half2(xh0, xh1);
        *(__half2*)(A_ + row + 256 + d0) = __halves2half2(xl0, xl1);
    }
}

// ---------------------------------------------------------------------------
// HMMA GEMM tile (proven R10 body): 128 px x 128 codes; 4 warps, 64x64 warp
// tile; 3-stage XOR-swizzled pipeline, ONE __syncthreads per chunk.
// ---------------------------------------------------------------------------
__device__ __forceinline__ void load_chunk3(uint32_t st, const char* Ag, const char* Bg,
                                            int p0, int nt, int kc, int tid) {
    const size_t aoff = (size_t)(kc & 7) * 128;
    const size_t boff = (size_t)kc * 128;
    #pragma unroll
    for (int i = 0; i < 8; ++i) {
        int o = tid + 128 * i;           // 0..1023
        int row = o >> 3, seg = (o & 7) * 16;
        const char* src = Ag + ((size_t)(p0 + row) << 10) + aoff + seg;
        uint32_t dst = st + row * 128 + (seg ^ ((row & 7) << 4));
        asm volatile("cp.async.cg.shared.global [%0], [%1], 16;" :: "r"(dst), "l"(src));
    }
    #pragma unroll
    for (int i = 0; i < 8; ++i) {
        int o = tid + 128 * i;
        int row = o >> 3, seg = (o & 7) * 16;
        const char* src = Bg + (size_t)(nt * 128 + row) * 1536 + boff + seg;
        uint32_t dst = st + 16384 + row * 128 + (seg ^ ((row & 7) << 4));
        asm volatile("cp.async.cg.shared.global [%0], [%1], 16;" :: "r"(dst), "l"(src));
    }
}

__global__ void __launch_bounds__(128, 2)
k_gemm(const __half* __restrict__ Ah, const __half* __restrict__ Bh,
       const float* __restrict__ s1g, const float* __restrict__ s2g,
       float* __restrict__ cand_d, int* __restrict__ cand_i) {
    extern __shared__ char sm[];
    uint32_t sb = smem_u32(sm);
    float* rd = (float*)sm;
    int*   ri = (int*)(sm + 1024);
    float* s2s = (float*)(sm + 2048);
    const uint32_t stg = sb + 4096;

    const int tid = threadIdx.x, lane = tid & 31, wid = tid >> 5;
    const int warp_m = wid & 1, warp_n = wid >> 1;    // 2M x 2N warp grid
    const int m0 = warp_m * 64, n0 = warp_n * 64;
    const int blk = blockIdx.x, pb = blk >> 3, nt = blk & 7;   // 8 code tiles
    const int p0 = pb * 128;
    const char* Ag = (const char*)Ah;
    const char* Bg = (const char*)Bh;

    s2s[tid] = s2g[nt * 128 + tid];

    const int rA = (lane & 7) + ((lane >> 3) & 1) * 8;
    const int cA = (lane >> 4) * 16;
    const int mA = (rA & 7) << 4;
    uint32_t arow[4];
    #pragma unroll
    for (int f = 0; f < 4; ++f) arow[f] = (uint32_t)(m0 + f * 16 + rA) * 128;
    const int rB = (lane & 7) + ((lane >> 4) << 3);
    const int cB = ((lane >> 3) & 1) * 16;
    const int mB = (rB & 7) << 4;
    uint32_t brow[4];
    #pragma unroll
    for (int g = 0; g < 4; ++g) brow[g] = (uint32_t)(n0 + g * 16 + rB) * 128;

    float s1v[8];
    #pragma unroll
    for (int s = 0; s < 8; ++s)
        s1v[s] = s1g[p0 + m0 + (s >> 1) * 16 + (lane >> 2) + (s & 1) * 8];

    float c[4][8][4];
    #pragma unroll
    for (int mf = 0; mf < 4; ++mf)
        #pragma unroll
        for (int j = 0; j < 8; ++j)
            #pragma unroll
            for (int q = 0; q < 4; ++q) c[mf][j][q] = 0.f;

    load_chunk3(stg,         Ag, Bg, p0, nt, 0, tid);
    asm volatile("cp.async.commit_group;" ::: "memory");
    load_chunk3(stg + 32768, Ag, Bg, p0, nt, 1, tid);
    asm volatile("cp.async.commit_group;" ::: "memory");

    for (int kc = 0; kc < 12; ++kc) {
        if (kc < 11) asm volatile("cp.async.wait_group 1;" ::: "memory");
        else         asm volatile("cp.async.wait_group 0;" ::: "memory");
        __syncthreads();
        if (kc + 2 < 12) {
            load_chunk3(stg + ((kc + 2) % 3) * 32768, Ag, Bg, p0, nt, kc + 2, tid);
            asm volatile("cp.async.commit_group;" ::: "memory");
        }

        const uint32_t sA = stg + (kc % 3) * 32768;
        const uint32_t sB = sA + 16384;
        #pragma unroll
        for (int ks = 0; ks < 4; ++ks) {
            const uint32_t colA = (uint32_t)((cA + ks * 32) ^ mA);
            const uint32_t colB = (uint32_t)((cB + ks * 32) ^ mB);
            uint32_t a[4][4], bf[4][4];
            #pragma unroll
            for (int f = 0; f < 4; ++f)
                LDSM4(a[f][0], a[f][1], a[f][2], a[f][3], sA + arow[f] + colA);
            #pragma unroll
            for (int g = 0; g < 4; ++g)
                LDSM4(bf[g][0], bf[g][1], bf[g][2], bf[g][3], sB + brow[g] + colB);

            #pragma unroll
            for (int f = 0; f < 4; ++f) {
                #pragma unroll
                for (int g = 0; g < 4; ++g) {
                    MMA16816(c[f][2*g][0], c[f][2*g][1], c[f][2*g][2], c[f][2*g][3],
                             a[f][0], a[f][1], a[f][2], a[f][3], bf[g][0], bf[g][1]);
                    MMA16816(c[f][2*g+1][0], c[f][2*g+1][1], c[f][2*g+1][2], c[f][2*g+1][3],
                             a[f][0], a[f][1], a[f][2], a[f][3], bf[g][2], bf[g][3]);
                }
            }
        }
    }

    const float SC = 0.001953125f;   // 2^-9
    float bd[8];
    int   bi[8];
    #pragma unroll
    for (int s = 0; s < 8; ++s) { bd[s] = 3.4e38f; bi[s] = 0; }
    #pragma unroll
    for (int mf = 0; mf < 4; ++mf) {
        #pragma unroll
        for (int j = 0; j < 8; ++j) {
            const int nl = n0 + j * 8 + ((lane & 3) << 1);
            const float s2a = s2s[nl], s2b = s2s[nl + 1];
            const int sl0 = mf * 2, sl1 = mf * 2 + 1;
            float d0 = (s1v[sl0] + s2a) - c[mf][j][0] * SC;
            float d1 = (s1v[sl0] + s2b) - c[mf][j][1] * SC;
            float d2 = (s1v[sl1] + s2a) - c[mf][j][2] * SC;
            float d3 = (s1v[sl1] + s2b) - c[mf][j][3] * SC;
            if (d0 < bd[sl0]) { bd[sl0] = d0; bi[sl0] = nl; }
            if (d1 < bd[sl0]) { bd[sl0] = d1; bi[sl0] = nl + 1; }
            if (d2 < bd[sl1]) { bd[sl1] = d2; bi[sl1] = nl; }
            if (d3 < bd[sl1]) { bd[sl1] = d3; bi[sl1] = nl + 1; }
        }
    }
    #pragma unroll
    for (int s = 0; s < 8; ++s) {
        #pragma unroll
        for (int off = 1; off <= 2; off <<= 1) {
            float od = __shfl_xor_sync(0xffffffffu, bd[s], off);
            int   oi = __shfl_xor_sync(0xffffffffu, bi[s], off);
            if (od < bd[s] || (od == bd[s] && oi < bi[s])) { bd[s] = od; bi[s] = oi; }
        }
    }
    __syncthreads();
    if ((lane & 3) == 0) {
        #pragma unroll
        for (int s = 0; s < 8; ++s) {
            int row = m0 + (s >> 1) * 16 + (lane >> 2) + (s & 1) * 8;
            rd[row * 2 + warp_n] = bd[s];
            ri[row * 2 + warp_n] = bi[s];
        }
    }
    __syncthreads();
    {
        float d0 = rd[tid * 2], d1 = rd[tid * 2 + 1];
        int i0 = ri[tid * 2], i1 = ri[tid * 2 + 1];
        bool t1 = (d1 < d0 || (d1 == d0 && i1 < i0));
        cand_d[(size_t)(p0 + tid) * 8 + nt] = t1 ? d1 : d0;
        cand_i[(size_t)(p0 + tid) * 8 + nt] = nt * 128 + (t1 ? i1 : i0);
    }
}

// ---------------------------------------------------------------------------
// fused: combine -> index + loss partial, then sector-efficient gather:
// warp-per-pixel coalesced cb row reads into qs[64][257], coalesced f4 writes.
// dynamic smem: qs 64*257*4 = 65792 B
// ---------------------------------------------------------------------------
__global__ void __launch_bounds__(256)
k_out(const float* __restrict__ cb,
      const float* __restrict__ cand_d, const int* __restrict__ cand_i,
      float* __restrict__ out, double* __restrict__ partial) {
    extern __shared__ float qs[];        // [64][257]
    __shared__ int idxs[128];
    __shared__ float sd[128];
    __shared__ double red[256];
    const int tid = threadIdx.x;
    const int w = tid >> 5, l = tid & 31;
    const int blk = blockIdx.x;
    const int b = blk >> 5, hw0 = (blk & 31) << 7;

    if (tid < 128) {
        const int pp = blk * 128 + tid;   // flat pixel index
        size_t base = (size_t)pp * 8;
        float bdv = cand_d[base]; int biv = cand_i[base];
        #pragma unroll
        for (int t = 1; t < 8; ++t) {
            float d = cand_d[base + t]; int i = cand_i[base + t];
            if (d < bdv || (d == bdv && i < biv)) { bdv = d; biv = i; }
        }
        idxs[tid] = biv;
        sd[tid] = bdv;
        out[IDX_OFF + pp] = (float)biv;
    }
    __syncthreads();

    // loss partial (deterministic double tree; same shape as R12)
    red[tid] = (tid < 128) ? (double)sd[tid] : 0.0;
    __syncthreads();
    #pragma unroll
    for (int s = 128; s > 0; s >>= 1) {
        if (tid < s) red[tid] += red[tid + s];
        __syncthreads();
    }
    if (tid == 0) partial[blk] = red[0];

    float* outb = out + ((size_t)b << 20);
    #pragma unroll
    for (int h = 0; h < 2; ++h) {
        // gather: warp w owns pixels lp = w*8 .. w*8+7 of this half
        #pragma unroll
        for (int r = 0; r < 8; ++r) {
            const int lp = w * 8 + r;
            const float* row = cb + (size_t)idxs[h * 64 + lp] * CDIM;
            float* q = qs + lp * 257;
            #pragma unroll
            for (int j = 0; j < 8; ++j)
                q[l + 32 * j] = row[l + 32 * j];   // coalesced 128B; bank (lp+l)%32
        }
        __syncthreads();
        // scatter: coalesced float4 stores over pixels
        for (int t = tid; t < 4096; t += 256) {
            int d = t >> 4, p4 = t & 15;
            float4 v;
            v.x = qs[(4 * p4 + 0) * 257 + d];
            v.y = qs[(4 * p4 + 1) * 257 + d];
            v.z = qs[(4 * p4 + 2) * 257 + d];
            v.w = qs[(4 * p4 + 3) * 257 + d];
            *(float4*)(outb + (size_t)d * HW + hw0 + h * 64 + 4 * p4) = v;
        }
        __syncthreads();
    }
}

__global__ void k_final(const double* __restrict__ partial, float* __restrict__ out) {
    __shared__ double red[256];
    int tid = threadIdx.x;
    red[tid] = partial[tid] + partial[tid + 256];
    __syncthreads();
    #pragma unroll
    for (int s = 128; s > 0; s >>= 1) {
        if (tid < s) red[tid] += red[tid + s];
        __syncthreads();
    }
    if (tid == 0) {
        double mse = red[0] / ((double)NPIX * (double)CDIM);
        out[LOSS_OFF] = (float)(1.25 * mse);
    }
}

// ---------------------------------------------------------------------------
extern "C" void kernel_launch(void* const* d_in, const int* in_sizes, int n_in,
                              void* d_out, int out_size) {
    (void)in_sizes; (void)n_in; (void)out_size;
    const float* in = (const float*)d_in[0];
    const float* cb = (const float*)d_in[1];
    float* out = (float*)d_out;

    __half* A_p; __half* B_p;
    float *s1_p, *s2_p, *cd_p; int* ci_p; double* part_p;
    cudaGetSymbolAddress((void**)&A_p,   g_A);
    cudaGetSymbolAddress((void**)&B_p,   g_B);
    cudaGetSymbolAddress((void**)&s1_p,  g_s1);
    cudaGetSymbolAddress((void**)&s2_p,  g_s2);
    cudaGetSymbolAddress((void**)&cd_p,  g_cand_d);
    cudaGetSymbolAddress((void**)&ci_p,  g_cand_i);
    cudaGetSymbolAddress((void**)&part_p, g_partial);

    const int smem_a = 256 * 37 * 4;             // 37888 -> ~6 CTAs/SM
    const int smem_g = 4096 + 3 * 32768;         // 102400
    const int smem_o = 64 * 257 * 4;             // 65792
    cudaFuncSetAttribute(k_split_a, cudaFuncAttributeMaxDynamicSharedMemorySize, smem_a);
    cudaFuncSetAttribute(k_gemm,    cudaFuncAttributeMaxDynamicSharedMemorySize, smem_g);
    cudaFuncSetAttribute(k_out,     cudaFuncAttributeMaxDynamicSharedMemorySize, smem_o);

    k_split_b<<<128, 256>>>(cb, B_p, s2_p);                           // idx 0
    k_split_a<<<2048, 256, smem_a>>>(in, A_p, s1_p);                  // idx 1
    k_gemm<<<4096, 128, smem_g>>>(A_p, B_p, s1_p, s2_p, cd_p, ci_p);  // idx 2
    k_out<<<NTILES, 256, smem_o>>>(cb, cd_p, ci_p, out, part_p);      // idx 3 -> ncu
    k_final<<<1, 256>>>(part_p, out);                                 // idx 4
}